// round 12
// baseline (speedup 1.0000x reference)
#include <cuda_runtime.h>
#include <cuda_bf16.h>
#include <math.h>
#include <float.h>

#define WAY 5
#define SHOT 5
#define QUERY 15
#define EMB 640
#define NMEM 100000
#define NSIM (SHOT + NMEM)   // 100005 candidates per way
#define TOPK 8
#define EPS 1e-12f
#define INV_TEMP (1.0f / 64.0f)

#define SPLITS 8             // scan splits per way in k3a
#define CHUNK ((NSIM + SPLITS - 1) / SPLITS)   // 12501

// ---- k2 pipeline geometry ----
#define K2_CTAS 296          // 2 per SM, exactly one wave
#define K2_WARPS 8
#define TILE_ROWS 32         // lane r owns row r
#define NTILES (NMEM / TILE_ROWS)      // 3125 (exact)
#define COLS_SLAB 8          // float4 columns per slab
#define SLABS 20             // 160 float4 cols / 8
#define NSTAGE 3
#define SLAB_BYTES (COLS_SLAB * TILE_ROWS * 16)   // 4096
#define K2_SMEM (WAY * EMB * 4 + K2_WARPS * NSTAGE * SLAB_BYTES)  // 12800+98304=111104

// ---------------- device scratch (static, allocation-free) ----------------
__device__ __align__(16) float g_c[WAY][EMB];   // per-way centroids
__device__ float g_sim[WAY][NSIM];              // similarity vector per way
__device__ float g_pv[WAY][SPLITS][TOPK];       // partial top-k values
__device__ int   g_pi[WAY][SPLITS][TOPK];       // partial top-k indices

typedef unsigned long long ull;

__device__ __forceinline__ float warp_sum(float v) {
#pragma unroll
    for (int o = 16; o; o >>= 1) v += __shfl_xor_sync(0xffffffffu, v, o);
    return v;
}

__device__ __forceinline__ unsigned ford(float f) {
    unsigned u = __float_as_uint(f);
    return (u & 0x80000000u) ? ~u : (u | 0x80000000u);
}

__device__ __forceinline__ void cp_async16(unsigned smem_dst, const void* gsrc) {
    asm volatile("cp.async.cg.shared.global [%0], [%1], 16;"
                 :: "r"(smem_dst), "l"(gsrc) : "memory");
}
__device__ __forceinline__ void cp_commit() {
    asm volatile("cp.async.commit_group;" ::: "memory");
}
__device__ __forceinline__ void cp_wait2() {         // wait all but 2 newest groups
    asm volatile("cp.async.wait_group 2;" ::: "memory");
}

// ---------------- dummy kernel (ncu launch-index alignment) -----------------
__global__ void k_dummy() {}

// ---------------- kernel 1: per-way support prep (grid = WAY) ---------------
__global__ void k1_support(const float* __restrict__ inst) {
    int w = blockIdx.x;
    int wid  = threadIdx.x >> 5;
    int lane = threadIdx.x & 31;

    __shared__ float sinv[SHOT];
    __shared__ float sc[EMB];

    if (wid < SHOT) {
        const float* row = inst + (size_t)(wid * WAY + w) * EMB;
        float ss = 0.f;
#pragma unroll
        for (int i = 0; i < 20; i++) {
            float v = row[lane + 32 * i];
            ss += v * v;
        }
        ss = warp_sum(ss);
        if (lane == 0) sinv[wid] = 1.0f / fmaxf(sqrtf(ss), EPS);
    }
    __syncthreads();

    for (int d = threadIdx.x; d < EMB; d += blockDim.x) {
        float s = 0.f;
#pragma unroll
        for (int t = 0; t < SHOT; t++)
            s += inst[(size_t)(t * WAY + w) * EMB + d] * sinv[t];
        s *= (1.0f / SHOT);
        sc[d] = s;
        g_c[w][d] = s;
    }
    __syncthreads();

    if (wid < SHOT) {
        const float* row = inst + (size_t)(wid * WAY + w) * EMB;
        float dot = 0.f;
#pragma unroll
        for (int i = 0; i < 20; i++) {
            int d = lane + 32 * i;
            dot += row[d] * sc[d];
        }
        dot = warp_sum(dot);
        if (lane == 0) g_sim[w][wid] = dot * sinv[wid];
    }
}

// ---------------- kernel 2: cp.async staged memory-bank scan ----------------
// Warp owns a 32-row tile; lane r owns row r. Slabs (8 f4-cols x 32 rows,
// column-major in smem) staged through a 3-deep per-warp cp.async ring.
// Each lane copies+consumes only its own row line => wait_group suffices.
__global__ void __launch_bounds__(256) k2_memscan(const float* __restrict__ mem) {
    extern __shared__ __align__(16) char dyn[];
    float4 (*scent)[EMB / 4] = reinterpret_cast<float4 (*)[EMB / 4]>(dyn);
    char* sbuf = dyn + WAY * EMB * 4;

    for (int i = threadIdx.x; i < WAY * EMB / 4; i += blockDim.x)
        (&scent[0][0])[i] = ((const float4*)g_c)[i];
    __syncthreads();

    int warp = threadIdx.x >> 5;
    int lane = threadIdx.x & 31;
    char* wbuf = sbuf + warp * (NSTAGE * SLAB_BYTES);
    unsigned wbase = (unsigned)__cvta_generic_to_shared(wbuf);

    int gw = blockIdx.x * K2_WARPS + warp;
    int stride = gridDim.x * K2_WARPS;

    for (int tile = gw; tile < NTILES; tile += stride) {
        // lane's row: 128 B per slab, contiguous along EMB
        const char* rowp = (const char*)mem + ((size_t)tile * TILE_ROWS + lane) * (EMB * 4);

        // prologue: stage slabs 0..NSTAGE-2
#pragma unroll
        for (int s = 0; s < NSTAGE - 1; s++) {
#pragma unroll
            for (int k = 0; k < COLS_SLAB; k++)
                cp_async16(wbase + s * SLAB_BYTES + k * (TILE_ROWS * 16) + lane * 16,
                           rowp + (s * COLS_SLAB + k) * 16);
            cp_commit();
        }

        float acc0 = 0.f, acc1 = 0.f, acc2 = 0.f, acc3 = 0.f, acc4 = 0.f, ssq = 0.f;

        for (int j = 0; j < SLABS; j++) {
            int pre = j + NSTAGE - 1;
            if (pre < SLABS) {
                int st = pre % NSTAGE;
#pragma unroll
                for (int k = 0; k < COLS_SLAB; k++)
                    cp_async16(wbase + st * SLAB_BYTES + k * (TILE_ROWS * 16) + lane * 16,
                               rowp + (pre * COLS_SLAB + k) * 16);
            }
            cp_commit();            // one group per iteration (possibly empty)
            cp_wait2();             // slab j resident

            const float4* col = (const float4*)(wbuf + (j % NSTAGE) * SLAB_BYTES);
#pragma unroll
            for (int k = 0; k < COLS_SLAB; k++) {
                float4 x = col[k * TILE_ROWS + lane];
                int cg = j * COLS_SLAB + k;
                float4 c0 = scent[0][cg], c1 = scent[1][cg], c2 = scent[2][cg],
                       c3 = scent[3][cg], c4 = scent[4][cg];
                ssq  += x.x * x.x  + x.y * x.y  + x.z * x.z  + x.w * x.w;
                acc0 += x.x * c0.x + x.y * c0.y + x.z * c0.z + x.w * c0.w;
                acc1 += x.x * c1.x + x.y * c1.y + x.z * c1.z + x.w * c1.w;
                acc2 += x.x * c2.x + x.y * c2.y + x.z * c2.z + x.w * c2.w;
                acc3 += x.x * c3.x + x.y * c3.y + x.z * c3.z + x.w * c3.w;
                acc4 += x.x * c4.x + x.y * c4.y + x.z * c4.z + x.w * c4.w;
            }
        }

        float inv = 1.0f / fmaxf(sqrtf(ssq), EPS);
        int row = SHOT + tile * TILE_ROWS + lane;
        g_sim[0][row] = acc0 * inv;
        g_sim[1][row] = acc1 * inv;
        g_sim[2][row] = acc2 * inv;
        g_sim[3][row] = acc3 * inv;
        g_sim[4][row] = acc4 * inv;
    }
}

// ---------------- top-k helpers ---------------------------------------------
__device__ __forceinline__ void merge8(float* av, int* ai,
                                       const float* bv, const int* bi) {
    float tv[TOPK]; int ti[TOPK];
    int ia = 0, ib = 0;
#pragma unroll
    for (int k = 0; k < TOPK; k++) {
        float va = av[ia], vb = bv[ib];
        bool takeA = (va > vb) || (va == vb && ai[ia] <= bi[ib]);
        if (takeA) { tv[k] = va; ti[k] = ai[ia]; ia++; }
        else       { tv[k] = vb; ti[k] = bi[ib]; ib++; }
    }
#pragma unroll
    for (int k = 0; k < TOPK; k++) { av[k] = tv[k]; ai[k] = ti[k]; }
}

__device__ __forceinline__ void insert8(float* bv, int* bi, float v, int i) {
    if (v > bv[TOPK - 1]) {
        int j = TOPK - 1;
        while (j > 0 && v > bv[j - 1]) { bv[j] = bv[j - 1]; bi[j] = bi[j - 1]; j--; }
        bv[j] = v; bi[j] = i;
    }
}

// ---------------- kernel 3a: partial top-8 (40 blocks) ----------------------
#define K3A_THREADS 256
__global__ void k3a_topk() {
    int w = blockIdx.x / SPLITS;
    int s = blockIdx.x % SPLITS;
    int lo = s * CHUNK;
    int hi = min(lo + CHUNK, NSIM);
    const float* sim = g_sim[w];
    int tid = threadIdx.x;

    float bv[TOPK]; int bi[TOPK];
#pragma unroll
    for (int j = 0; j < TOPK; j++) { bv[j] = -FLT_MAX; bi[j] = 0x7fffffff; }

    int i = lo + tid;
    for (; i + 3 * K3A_THREADS < hi; i += 4 * K3A_THREADS) {
        float v0 = sim[i];
        float v1 = sim[i + K3A_THREADS];
        float v2 = sim[i + 2 * K3A_THREADS];
        float v3 = sim[i + 3 * K3A_THREADS];
        insert8(bv, bi, v0, i);
        insert8(bv, bi, v1, i + K3A_THREADS);
        insert8(bv, bi, v2, i + 2 * K3A_THREADS);
        insert8(bv, bi, v3, i + 3 * K3A_THREADS);
    }
    for (; i < hi; i += K3A_THREADS) insert8(bv, bi, sim[i], i);

    __shared__ float shv[K3A_THREADS][TOPK];
    __shared__ int   shi[K3A_THREADS][TOPK];
#pragma unroll
    for (int j = 0; j < TOPK; j++) { shv[tid][j] = bv[j]; shi[tid][j] = bi[j]; }
    __syncthreads();

    for (int step = K3A_THREADS / 2; step >= 1; step >>= 1) {
        if (tid < step)
            merge8(shv[tid], shi[tid], shv[tid + step], shi[tid + step]);
        __syncthreads();
    }
    if (tid < TOPK) {
        g_pv[w][s][tid] = shv[0][tid];
        g_pi[w][s][tid] = shi[0][tid];
    }
}

// ---------------- kernel 3b: warp-parallel merge + proto + logits -----------
__global__ void k3b_proto_logits(const float* __restrict__ inst,
                                 const float* __restrict__ mem,
                                 float* __restrict__ out) {
    int w = blockIdx.x;
    int tid = threadIdx.x;
    int lane = tid & 31, wid = tid >> 5;

    __shared__ float cv[SPLITS * TOPK];
    __shared__ int   cx[SPLITS * TOPK];
    __shared__ float svals[TOPK];
    __shared__ int   sidx[TOPK];
    __shared__ float red[32];
    __shared__ float sp[EMB];

    if (tid < SPLITS * TOPK) {
        cv[tid] = (&g_pv[w][0][0])[tid];
        cx[tid] = (&g_pi[w][0][0])[tid];
    }
    __syncthreads();

    // warp 0: parallel top-8 over 64 candidates via packed u64 keys
    if (wid == 0) {
        float v0 = cv[lane],      v1 = cv[lane + 32];
        int   x0 = cx[lane],      x1 = cx[lane + 32];
        ull k0 = ((ull)ford(v0) << 32) | (unsigned)(0x7fffffff - x0);
        ull k1 = ((ull)ford(v1) << 32) | (unsigned)(0x7fffffff - x1);
#pragma unroll
        for (int j = 0; j < TOPK; j++) {
            ull m = k0 > k1 ? k0 : k1;
#pragma unroll
            for (int o = 16; o; o >>= 1) {
                ull t = __shfl_xor_sync(0xffffffffu, m, o);
                if (t > m) m = t;
            }
            if (k0 == m) { svals[j] = v0; sidx[j] = x0; k0 = 0ull; }
            else if (k1 == m) { svals[j] = v1; sidx[j] = x1; k1 = 0ull; }
        }
    }
    __syncthreads();

    float denom = 0.f;
#pragma unroll
    for (int j = 0; j < TOPK; j++) denom += svals[j];

    float numer = 0.f;
#pragma unroll
    for (int j = 0; j < TOPK; j++) {
        int idx = sidx[j];
        const float* src = (idx < SHOT)
            ? inst + (size_t)(idx * WAY + w) * EMB
            : mem + (size_t)(idx - SHOT) * EMB;
        numer += svals[j] * src[tid];
    }
    float p = numer / denom;

    float ss = warp_sum(p * p);
    if (lane == 0) red[wid] = ss;
    __syncthreads();
    if (wid == 0) {
        float t = (lane < 20) ? red[lane] : 0.f;
        t = warp_sum(t);
        if (lane == 0) red[0] = INV_TEMP / fmaxf(sqrtf(t), EPS);
    }
    __syncthreads();
    sp[tid] = p * red[0];
    __syncthreads();

    for (int q = wid; q < QUERY * WAY; q += 20) {
        const float* qr = inst + (size_t)(SHOT * WAY + q) * EMB;
        float dot = 0.f;
#pragma unroll
        for (int i = 0; i < 20; i++) {
            int d = lane + 32 * i;
            dot += qr[d] * sp[d];
        }
        dot = warp_sum(dot);
        if (lane == 0) out[q * WAY + w] = dot;
    }
}

// ---------------- launch ----------------------------------------------------
extern "C" void kernel_launch(void* const* d_in, const int* in_sizes, int n_in,
                              void* d_out, int out_size) {
    const float* inst = (const float*)d_in[0];   // [100, 640] fp32
    const float* mem  = (const float*)d_in[1];   // [100000, 640] fp32
    float* out = (float*)d_out;                  // [75, 5] fp32

    static int smem_set = 0;
    if (!smem_set) {
        cudaFuncSetAttribute(k2_memscan,
                             cudaFuncAttributeMaxDynamicSharedMemorySize, K2_SMEM);
        smem_set = 1;
    }

    k1_support<<<WAY, 256>>>(inst);

    // one no-op launch so k2 sits at global launch index 3 (ncu capture slot)
    k_dummy<<<1, 32>>>();

    k2_memscan<<<K2_CTAS, 256, K2_SMEM>>>(mem);

    k3a_topk<<<WAY * SPLITS, K3A_THREADS>>>();
    k3b_proto_logits<<<WAY, 640>>>(inst, mem, out);
}

// round 13
// speedup vs baseline: 1.5584x; 1.5584x over previous
#include <cuda_runtime.h>
#include <cuda_bf16.h>
#include <math.h>
#include <float.h>

#define WAY 5
#define SHOT 5
#define QUERY 15
#define EMB 640
#define NMEM 100000
#define NSIM (SHOT + NMEM)   // 100005 candidates per way
#define TOPK 8
#define EPS 1e-12f
#define INV_TEMP (1.0f / 64.0f)

#define ROWS 4               // rows per warp in k2
#define SPLITS 64            // scan splits per way in k3a
#define CHUNK ((NSIM + SPLITS - 1) / SPLITS)   // 1563

// ---------------- device scratch (static, allocation-free) ----------------
__device__ __align__(16) float g_c[WAY][EMB];   // per-way centroids
__device__ float g_sim[WAY][NSIM];              // similarity vector per way
__device__ float g_pv[WAY][SPLITS][TOPK];       // partial top-k values
__device__ int   g_pi[WAY][SPLITS][TOPK];       // partial top-k indices

typedef unsigned long long ull;

__device__ __forceinline__ float warp_sum(float v) {
#pragma unroll
    for (int o = 16; o; o >>= 1) v += __shfl_xor_sync(0xffffffffu, v, o);
    return v;
}

// orderable-uint transform: key order == float order
__device__ __forceinline__ unsigned ford(float f) {
    unsigned u = __float_as_uint(f);
    return (u & 0x80000000u) ? ~u : (u | 0x80000000u);
}
__device__ __forceinline__ unsigned unford(unsigned u) {
    return (u & 0x80000000u) ? (u & 0x7fffffffu) : ~u;
}

// ---------------- dummy kernel (ncu launch-index alignment) -----------------
__global__ void k_dummy() {}

// ---------------- kernel 1: per-way support prep (grid = WAY) ---------------
__global__ void k1_support(const float* __restrict__ inst) {
    int w = blockIdx.x;
    int wid  = threadIdx.x >> 5;
    int lane = threadIdx.x & 31;

    __shared__ float sinv[SHOT];
    __shared__ float sc[EMB];

    if (wid < SHOT) {
        const float* row = inst + (size_t)(wid * WAY + w) * EMB;
        float ss = 0.f;
#pragma unroll
        for (int i = 0; i < 20; i++) {
            float v = row[lane + 32 * i];
            ss += v * v;
        }
        ss = warp_sum(ss);
        if (lane == 0) sinv[wid] = 1.0f / fmaxf(sqrtf(ss), EPS);
    }
    __syncthreads();

    for (int d = threadIdx.x; d < EMB; d += blockDim.x) {
        float s = 0.f;
#pragma unroll
        for (int t = 0; t < SHOT; t++)
            s += inst[(size_t)(t * WAY + w) * EMB + d] * sinv[t];
        s *= (1.0f / SHOT);
        sc[d] = s;
        g_c[w][d] = s;
    }
    __syncthreads();

    if (wid < SHOT) {
        const float* row = inst + (size_t)(wid * WAY + w) * EMB;
        float dot = 0.f;
#pragma unroll
        for (int i = 0; i < 20; i++) {
            int d = lane + 32 * i;
            dot += row[d] * sc[d];
        }
        dot = warp_sum(dot);
        if (lane == 0) g_sim[w][wid] = dot * sinv[wid];
    }
}

// ---------------- kernel 2: memory-bank scan (R11 proven body, 63us) --------
__global__ void __launch_bounds__(256, 2) k2_memscan(const float* __restrict__ mem) {
    __shared__ float4 sc[WAY][EMB / 4];   // centroids, 12.8 KB
    for (int i = threadIdx.x; i < WAY * EMB / 4; i += blockDim.x)
        (&sc[0][0])[i] = ((const float4*)g_c)[i];
    __syncthreads();

    int wg   = (blockIdx.x * blockDim.x + threadIdx.x) >> 5;
    int lane = threadIdx.x & 31;
    int row0 = wg * ROWS;
    if (row0 >= NMEM) return;

    const float4* base = (const float4*)(mem + (size_t)row0 * EMB);  // row stride 160

    float acc[ROWS][6];
#pragma unroll
    for (int r = 0; r < ROWS; r++)
#pragma unroll
        for (int k = 0; k < 6; k++) acc[r][k] = 0.f;

    // prefetch chunk 0
    float4 v[ROWS];
#pragma unroll
    for (int r = 0; r < ROWS; r++) v[r] = __ldg(base + (size_t)r * 160 + lane);

#pragma unroll
    for (int i = 0; i < 5; i++) {
        int ci = lane + 32 * i;

        float4 nx[ROWS];
        if (i < 4) {
#pragma unroll
            for (int r = 0; r < ROWS; r++)
                nx[r] = __ldg(base + (size_t)r * 160 + ci + 32);
        }

        float4 c0 = sc[0][ci], c1 = sc[1][ci], c2 = sc[2][ci],
               c3 = sc[3][ci], c4 = sc[4][ci];
#pragma unroll
        for (int r = 0; r < ROWS; r++) {
            float4 x = v[r];
            acc[r][5] += x.x * x.x  + x.y * x.y  + x.z * x.z  + x.w * x.w;
            acc[r][0] += x.x * c0.x + x.y * c0.y + x.z * c0.z + x.w * c0.w;
            acc[r][1] += x.x * c1.x + x.y * c1.y + x.z * c1.z + x.w * c1.w;
            acc[r][2] += x.x * c2.x + x.y * c2.y + x.z * c2.z + x.w * c2.w;
            acc[r][3] += x.x * c3.x + x.y * c3.y + x.z * c3.z + x.w * c3.w;
            acc[r][4] += x.x * c4.x + x.y * c4.y + x.z * c4.z + x.w * c4.w;
        }
        if (i < 4) {
#pragma unroll
            for (int r = 0; r < ROWS; r++) v[r] = nx[r];
        }
    }

#pragma unroll
    for (int r = 0; r < ROWS; r++) {
#pragma unroll
        for (int o = 16; o; o >>= 1) {
#pragma unroll
            for (int k = 0; k < 6; k++)
                acc[r][k] += __shfl_xor_sync(0xffffffffu, acc[r][k], o);
        }
        float inv = 1.0f / fmaxf(sqrtf(acc[r][5]), EPS);
        if (lane < WAY) {
            float a = (lane == 0) ? acc[r][0] :
                      (lane == 1) ? acc[r][1] :
                      (lane == 2) ? acc[r][2] :
                      (lane == 3) ? acc[r][3] : acc[r][4];
            g_sim[lane][SHOT + row0 + r] = a * inv;
        }
    }
}

// ---------------- top-k helpers ---------------------------------------------
// register-resident insert: static indices only (no local-memory spill).
// swap-bubble: carries the displaced element down the sorted array.
__device__ __forceinline__ void insert8(float* bv, int* bi, float v, int i) {
    if (v > bv[TOPK - 1]) {
        float cv = v; int ci = i;
#pragma unroll
        for (int j = 0; j < TOPK; j++) {
            if (cv > bv[j]) {
                float tv = bv[j]; bv[j] = cv; cv = tv;
                int   ti = bi[j]; bi[j] = ci; ci = ti;
            }
        }
    }
}

// merge of two sorted 8-lists held in SHARED memory (dynamic idx ok: LDS)
__device__ __forceinline__ void merge8(float* av, int* ai,
                                       const float* bv, const int* bi) {
    float tv[TOPK]; int ti[TOPK];
    int ia = 0, ib = 0;
#pragma unroll
    for (int k = 0; k < TOPK; k++) {
        float va = av[ia], vb = bv[ib];
        bool takeA = (va > vb) || (va == vb && ai[ia] <= bi[ib]);
        if (takeA) { tv[k] = va; ti[k] = ai[ia]; ia++; }
        else       { tv[k] = vb; ti[k] = bi[ib]; ib++; }
    }
#pragma unroll
    for (int k = 0; k < TOPK; k++) { av[k] = tv[k]; ai[k] = ti[k]; }
}

// ---------------- kernel 3a: partial top-8 (320 blocks) ---------------------
#define K3A_THREADS 256
__global__ void k3a_topk() {
    int w = blockIdx.x / SPLITS;
    int s = blockIdx.x % SPLITS;
    int lo = s * CHUNK;
    int hi = min(lo + CHUNK, NSIM);
    const float* sim = g_sim[w];
    int tid = threadIdx.x;

    float bv[TOPK]; int bi[TOPK];
#pragma unroll
    for (int j = 0; j < TOPK; j++) { bv[j] = -FLT_MAX; bi[j] = 0x7fffffff; }

    int i = lo + tid;
    for (; i + 3 * K3A_THREADS < hi; i += 4 * K3A_THREADS) {
        float v0 = sim[i];
        float v1 = sim[i + K3A_THREADS];
        float v2 = sim[i + 2 * K3A_THREADS];
        float v3 = sim[i + 3 * K3A_THREADS];
        insert8(bv, bi, v0, i);
        insert8(bv, bi, v1, i + K3A_THREADS);
        insert8(bv, bi, v2, i + 2 * K3A_THREADS);
        insert8(bv, bi, v3, i + 3 * K3A_THREADS);
    }
    for (; i < hi; i += K3A_THREADS) insert8(bv, bi, sim[i], i);

    __shared__ float shv[K3A_THREADS][TOPK];
    __shared__ int   shi[K3A_THREADS][TOPK];
#pragma unroll
    for (int j = 0; j < TOPK; j++) { shv[tid][j] = bv[j]; shi[tid][j] = bi[j]; }
    __syncthreads();

    for (int step = K3A_THREADS / 2; step >= 1; step >>= 1) {
        if (tid < step)
            merge8(shv[tid], shi[tid], shv[tid + step], shi[tid + step]);
        __syncthreads();
    }
    if (tid < TOPK) {
        g_pv[w][s][tid] = shv[0][tid];
        g_pi[w][s][tid] = shi[0][tid];
    }
}

// ---------------- kernel 3b: warp-parallel merge + proto + logits -----------
// grid = WAY, 640 threads; warp 0 selects top-8 of 512 candidates via packed keys
__global__ void k3b_proto_logits(const float* __restrict__ inst,
                                 const float* __restrict__ mem,
                                 float* __restrict__ out) {
    int w = blockIdx.x;
    int tid = threadIdx.x;
    int lane = tid & 31, wid = tid >> 5;

    __shared__ float cv[SPLITS * TOPK];    // 512
    __shared__ int   cx[SPLITS * TOPK];
    __shared__ float svals[TOPK];
    __shared__ int   sidx[TOPK];
    __shared__ float red[32];
    __shared__ float sp[EMB];

    if (tid < SPLITS * TOPK) {
        cv[tid] = (&g_pv[w][0][0])[tid];
        cx[tid] = (&g_pi[w][0][0])[tid];
    }
    __syncthreads();

    // warp 0: top-8 of 512 via packed u64 keys (16 keys per lane)
    // key = (ford(v) << 32) | (0x7fffffff - idx): max key = max value,
    // ties -> smaller index; keys unique (indices unique).
    if (wid == 0) {
        ull k[16];
#pragma unroll
        for (int t = 0; t < 16; t++) {
            float v = cv[lane + 32 * t];
            int   x = cx[lane + 32 * t];
            k[t] = ((ull)ford(v) << 32) | (unsigned)(0x7fffffff - x);
        }
#pragma unroll
        for (int j = 0; j < TOPK; j++) {
            ull m = k[0];
#pragma unroll
            for (int t = 1; t < 16; t++) m = (k[t] > m) ? k[t] : m;
#pragma unroll
            for (int o = 16; o; o >>= 1) {
                ull t2 = __shfl_xor_sync(0xffffffffu, m, o);
                if (t2 > m) m = t2;
            }
            // clear the winner (unique key) in whichever lane holds it
#pragma unroll
            for (int t = 0; t < 16; t++)
                if (k[t] == m) k[t] = 0ull;
            if (lane == 0) {
                svals[j] = __uint_as_float(unford((unsigned)(m >> 32)));
                sidx[j]  = 0x7fffffff - (int)(unsigned)(m & 0xffffffffu);
            }
        }
    }
    __syncthreads();

    float denom = 0.f;
#pragma unroll
    for (int j = 0; j < TOPK; j++) denom += svals[j];

    float numer = 0.f;
#pragma unroll
    for (int j = 0; j < TOPK; j++) {
        int idx = sidx[j];
        const float* src = (idx < SHOT)
            ? inst + (size_t)(idx * WAY + w) * EMB
            : mem + (size_t)(idx - SHOT) * EMB;
        numer += svals[j] * src[tid];
    }
    float p = numer / denom;

    float ss = warp_sum(p * p);
    if (lane == 0) red[wid] = ss;
    __syncthreads();
    if (wid == 0) {
        float t = (lane < 20) ? red[lane] : 0.f;
        t = warp_sum(t);
        if (lane == 0) red[0] = INV_TEMP / fmaxf(sqrtf(t), EPS);
    }
    __syncthreads();
    sp[tid] = p * red[0];
    __syncthreads();

    for (int q = wid; q < QUERY * WAY; q += 20) {
        const float* qr = inst + (size_t)(SHOT * WAY + q) * EMB;
        float dot = 0.f;
#pragma unroll
        for (int i = 0; i < 20; i++) {
            int d = lane + 32 * i;
            dot += qr[d] * sp[d];
        }
        dot = warp_sum(dot);
        if (lane == 0) out[q * WAY + w] = dot;
    }
}

// ---------------- launch ----------------------------------------------------
extern "C" void kernel_launch(void* const* d_in, const int* in_sizes, int n_in,
                              void* d_out, int out_size) {
    const float* inst = (const float*)d_in[0];   // [100, 640] fp32
    const float* mem  = (const float*)d_in[1];   // [100000, 640] fp32
    float* out = (float*)d_out;                  // [75, 5] fp32

    k1_support<<<WAY, 256>>>(inst);

    // one no-op launch so the NEW k3a sits at ncu capture slot 3
    k_dummy<<<1, 32>>>();

    int warps  = (NMEM + ROWS - 1) / ROWS;       // 25000
    int blocks = (warps + 7) / 8;                // 3125
    k2_memscan<<<blocks, 256>>>(mem);

    k3a_topk<<<WAY * SPLITS, K3A_THREADS>>>();
    k3b_proto_logits<<<WAY, 640>>>(inst, mem, out);
}

// round 14
// speedup vs baseline: 1.5686x; 1.0065x over previous
#include <cuda_runtime.h>
#include <cuda_bf16.h>
#include <math.h>
#include <float.h>

#define WAY 5
#define SHOT 5
#define QUERY 15
#define EMB 640
#define NMEM 100000
#define NSIM (SHOT + NMEM)   // 100005 candidates per way
#define TOPK 8
#define EPS 1e-12f
#define INV_TEMP (1.0f / 64.0f)

#define ROWS 8               // rows per warp in k2 (batched loads)
#define SPLITS 32            // scan splits per way in k3a
#define CHUNK ((NSIM + SPLITS - 1) / SPLITS)   // 3126

// ---------------- device scratch (static, allocation-free) ----------------
__device__ __align__(16) float g_c[WAY][EMB];   // per-way centroids
__device__ float g_sim[WAY][NSIM];              // similarity vector per way
__device__ float g_pv[WAY][SPLITS][TOPK];       // partial top-k values
__device__ int   g_pi[WAY][SPLITS][TOPK];       // partial top-k indices

typedef unsigned long long ull;

__device__ __forceinline__ float warp_sum(float v) {
#pragma unroll
    for (int o = 16; o; o >>= 1) v += __shfl_xor_sync(0xffffffffu, v, o);
    return v;
}

// orderable-uint transform: key order == float order
__device__ __forceinline__ unsigned ford(float f) {
    unsigned u = __float_as_uint(f);
    return (u & 0x80000000u) ? ~u : (u | 0x80000000u);
}
__device__ __forceinline__ unsigned unford(unsigned u) {
    return (u & 0x80000000u) ? (u & 0x7fffffffu) : ~u;
}
__device__ __forceinline__ ull warp_max_u64(ull m) {
#pragma unroll
    for (int o = 16; o; o >>= 1) {
        ull t = __shfl_xor_sync(0xffffffffu, m, o);
        if (t > m) m = t;
    }
    return m;
}

// ---------------- dummy kernel (ncu launch-index alignment) -----------------
__global__ void k_dummy() {}

// ---------------- kernel 1: per-way support prep (grid = WAY) ---------------
__global__ void k1_support(const float* __restrict__ inst) {
    int w = blockIdx.x;
    int wid  = threadIdx.x >> 5;
    int lane = threadIdx.x & 31;

    __shared__ float sinv[SHOT];
    __shared__ float sc[EMB];

    if (wid < SHOT) {
        const float* row = inst + (size_t)(wid * WAY + w) * EMB;
        float ss = 0.f;
#pragma unroll
        for (int i = 0; i < 20; i++) {
            float v = row[lane + 32 * i];
            ss += v * v;
        }
        ss = warp_sum(ss);
        if (lane == 0) sinv[wid] = 1.0f / fmaxf(sqrtf(ss), EPS);
    }
    __syncthreads();

    for (int d = threadIdx.x; d < EMB; d += blockDim.x) {
        float s = 0.f;
#pragma unroll
        for (int t = 0; t < SHOT; t++)
            s += inst[(size_t)(t * WAY + w) * EMB + d] * sinv[t];
        s *= (1.0f / SHOT);
        sc[d] = s;
        g_c[w][d] = s;
    }
    __syncthreads();

    if (wid < SHOT) {
        const float* row = inst + (size_t)(wid * WAY + w) * EMB;
        float dot = 0.f;
#pragma unroll
        for (int i = 0; i < 20; i++) {
            int d = lane + 32 * i;
            dot += row[d] * sc[d];
        }
        dot = warp_sum(dot);
        if (lane == 0) g_sim[w][wid] = dot * sinv[wid];
    }
}

// ---------------- kernel 2: memory-bank scan (ROWS=8, batched bursts) -------
// 8 rows/warp: halves LDS bytes per LDG byte, 8 LDG.128 burst per chunk.
__global__ void __launch_bounds__(256, 2) k2_memscan(const float* __restrict__ mem) {
    __shared__ float4 sc[WAY][EMB / 4];   // centroids, 12.8 KB
    for (int i = threadIdx.x; i < WAY * EMB / 4; i += blockDim.x)
        (&sc[0][0])[i] = ((const float4*)g_c)[i];
    __syncthreads();

    int wg   = (blockIdx.x * blockDim.x + threadIdx.x) >> 5;
    int lane = threadIdx.x & 31;
    int row0 = wg * ROWS;
    if (row0 >= NMEM) return;

    const float4* base = (const float4*)(mem + (size_t)row0 * EMB);  // row stride 160

    float acc[ROWS][6];
#pragma unroll
    for (int r = 0; r < ROWS; r++)
#pragma unroll
        for (int k = 0; k < 6; k++) acc[r][k] = 0.f;

#pragma unroll
    for (int i = 0; i < 5; i++) {
        int ci = lane + 32 * i;
        // batched burst: 8 independent LDG.128 issued before any consumer
        float4 v[ROWS];
#pragma unroll
        for (int r = 0; r < ROWS; r++) v[r] = __ldg(base + (size_t)r * 160 + ci);

        float4 c0 = sc[0][ci], c1 = sc[1][ci], c2 = sc[2][ci],
               c3 = sc[3][ci], c4 = sc[4][ci];
#pragma unroll
        for (int r = 0; r < ROWS; r++) {
            float4 x = v[r];
            acc[r][5] += x.x * x.x  + x.y * x.y  + x.z * x.z  + x.w * x.w;
            acc[r][0] += x.x * c0.x + x.y * c0.y + x.z * c0.z + x.w * c0.w;
            acc[r][1] += x.x * c1.x + x.y * c1.y + x.z * c1.z + x.w * c1.w;
            acc[r][2] += x.x * c2.x + x.y * c2.y + x.z * c2.z + x.w * c2.w;
            acc[r][3] += x.x * c3.x + x.y * c3.y + x.z * c3.z + x.w * c3.w;
            acc[r][4] += x.x * c4.x + x.y * c4.y + x.z * c4.z + x.w * c4.w;
        }
    }

#pragma unroll
    for (int r = 0; r < ROWS; r++) {
#pragma unroll
        for (int o = 16; o; o >>= 1) {
#pragma unroll
            for (int k = 0; k < 6; k++)
                acc[r][k] += __shfl_xor_sync(0xffffffffu, acc[r][k], o);
        }
        float inv = 1.0f / fmaxf(sqrtf(acc[r][5]), EPS);
        if (lane < WAY) {
            float a = (lane == 0) ? acc[r][0] :
                      (lane == 1) ? acc[r][1] :
                      (lane == 2) ? acc[r][2] :
                      (lane == 3) ? acc[r][3] : acc[r][4];
            g_sim[lane][SHOT + row0 + r] = a * inv;
        }
    }
}

// ---------------- register-resident insert (static indices only) ------------
__device__ __forceinline__ void insert8(float* bv, int* bi, float v, int i) {
    if (v > bv[TOPK - 1]) {
        float cv = v; int ci = i;
#pragma unroll
        for (int j = 0; j < TOPK; j++) {
            if (cv > bv[j]) {
                float tv = bv[j]; bv[j] = cv; cv = tv;
                int   ti = bi[j]; bi[j] = ci; ci = ti;
            }
        }
    }
}

// ---------------- kernel 3a: partial top-8 (160 blocks, warp-level merge) ---
#define K3A_THREADS 256
__global__ void k3a_topk() {
    int w = blockIdx.x / SPLITS;
    int s = blockIdx.x % SPLITS;
    int lo = s * CHUNK;
    int hi = min(lo + CHUNK, NSIM);
    const float* sim = g_sim[w];
    int tid = threadIdx.x;
    int lane = tid & 31, wid = tid >> 5;

    float bv[TOPK]; int bi[TOPK];
#pragma unroll
    for (int j = 0; j < TOPK; j++) { bv[j] = -FLT_MAX; bi[j] = 0x7fffffff; }

    int i = lo + tid;
    for (; i + 3 * K3A_THREADS < hi; i += 4 * K3A_THREADS) {
        float v0 = sim[i];
        float v1 = sim[i + K3A_THREADS];
        float v2 = sim[i + 2 * K3A_THREADS];
        float v3 = sim[i + 3 * K3A_THREADS];
        insert8(bv, bi, v0, i);
        insert8(bv, bi, v1, i + K3A_THREADS);
        insert8(bv, bi, v2, i + 2 * K3A_THREADS);
        insert8(bv, bi, v3, i + 3 * K3A_THREADS);
    }
    for (; i < hi; i += K3A_THREADS) insert8(bv, bi, sim[i], i);

    // pack to orderable u64 keys (unique: indices unique)
    ull k[TOPK];
#pragma unroll
    for (int j = 0; j < TOPK; j++)
        k[j] = ((ull)ford(bv[j]) << 32) | (unsigned)(0x7fffffff - bi[j]);

    // per-warp top-8 extraction (no smem tree)
    __shared__ ull swarp[K3A_THREADS / 32][TOPK];   // 8 warps x 8 keys
#pragma unroll
    for (int j = 0; j < TOPK; j++) {
        ull loc = k[0];
#pragma unroll
        for (int t = 1; t < TOPK; t++) loc = (k[t] > loc) ? k[t] : loc;
        ull m = warp_max_u64(loc);
#pragma unroll
        for (int t = 0; t < TOPK; t++)
            if (k[t] == m) k[t] = 0ull;
        if (lane == 0) swarp[wid][j] = m;
    }
    __syncthreads();

    // warp 0: merge 64 keys (2 per lane), extract top-8, write out
    if (wid == 0) {
        ull a = (&swarp[0][0])[lane];
        ull b = (&swarp[0][0])[lane + 32];
#pragma unroll
        for (int j = 0; j < TOPK; j++) {
            ull loc = (a > b) ? a : b;
            ull m = warp_max_u64(loc);
            if (a == m) a = 0ull;
            if (b == m) b = 0ull;
            if (lane == 0) {
                g_pv[w][s][j] = __uint_as_float(unford((unsigned)(m >> 32)));
                g_pi[w][s][j] = 0x7fffffff - (int)(unsigned)(m & 0xffffffffu);
            }
        }
    }
}

// ---------------- kernel 3b: warp-parallel merge + proto + logits -----------
// grid = WAY, 640 threads; warp 0 selects top-8 of 256 candidates
__global__ void k3b_proto_logits(const float* __restrict__ inst,
                                 const float* __restrict__ mem,
                                 float* __restrict__ out) {
    int w = blockIdx.x;
    int tid = threadIdx.x;
    int lane = tid & 31, wid = tid >> 5;

    __shared__ float cv[SPLITS * TOPK];    // 256
    __shared__ int   cx[SPLITS * TOPK];
    __shared__ float svals[TOPK];
    __shared__ int   sidx[TOPK];
    __shared__ float red[32];
    __shared__ float sp[EMB];

    if (tid < SPLITS * TOPK) {
        cv[tid] = (&g_pv[w][0][0])[tid];
        cx[tid] = (&g_pi[w][0][0])[tid];
    }
    __syncthreads();

    // warp 0: top-8 of 256 via packed u64 keys (8 per lane)
    if (wid == 0) {
        ull k[8];
#pragma unroll
        for (int t = 0; t < 8; t++) {
            float v = cv[lane + 32 * t];
            int   x = cx[lane + 32 * t];
            k[t] = ((ull)ford(v) << 32) | (unsigned)(0x7fffffff - x);
        }
#pragma unroll
        for (int j = 0; j < TOPK; j++) {
            ull loc = k[0];
#pragma unroll
            for (int t = 1; t < 8; t++) loc = (k[t] > loc) ? k[t] : loc;
            ull m = warp_max_u64(loc);
#pragma unroll
            for (int t = 0; t < 8; t++)
                if (k[t] == m) k[t] = 0ull;
            if (lane == 0) {
                svals[j] = __uint_as_float(unford((unsigned)(m >> 32)));
                sidx[j]  = 0x7fffffff - (int)(unsigned)(m & 0xffffffffu);
            }
        }
    }
    __syncthreads();

    float denom = 0.f;
#pragma unroll
    for (int j = 0; j < TOPK; j++) denom += svals[j];

    float numer = 0.f;
#pragma unroll
    for (int j = 0; j < TOPK; j++) {
        int idx = sidx[j];
        const float* src = (idx < SHOT)
            ? inst + (size_t)(idx * WAY + w) * EMB
            : mem + (size_t)(idx - SHOT) * EMB;
        numer += svals[j] * src[tid];
    }
    float p = numer / denom;

    float ss = warp_sum(p * p);
    if (lane == 0) red[wid] = ss;
    __syncthreads();
    if (wid == 0) {
        float t = (lane < 20) ? red[lane] : 0.f;
        t = warp_sum(t);
        if (lane == 0) red[0] = INV_TEMP / fmaxf(sqrtf(t), EPS);
    }
    __syncthreads();
    sp[tid] = p * red[0];
    __syncthreads();

    for (int q = wid; q < QUERY * WAY; q += 20) {
        const float* qr = inst + (size_t)(SHOT * WAY + q) * EMB;
        float dot = 0.f;
#pragma unroll
        for (int i = 0; i < 20; i++) {
            int d = lane + 32 * i;
            dot += qr[d] * sp[d];
        }
        dot = warp_sum(dot);
        if (lane == 0) out[q * WAY + w] = dot;
    }
}

// ---------------- launch ----------------------------------------------------
extern "C" void kernel_launch(void* const* d_in, const int* in_sizes, int n_in,
                              void* d_out, int out_size) {
    const float* inst = (const float*)d_in[0];   // [100, 640] fp32
    const float* mem  = (const float*)d_in[1];   // [100000, 640] fp32
    float* out = (float*)d_out;                  // [75, 5] fp32

    k1_support<<<WAY, 256>>>(inst);

    // two no-op launches so k2 sits at ncu capture slot 3
    k_dummy<<<1, 32>>>();
    k_dummy<<<1, 32>>>();

    int warps  = (NMEM + ROWS - 1) / ROWS;       // 12500
    int blocks = (warps + 7) / 8;                // 1563
    k2_memscan<<<blocks, 256>>>(mem);

    k3a_topk<<<WAY * SPLITS, K3A_THREADS>>>();
    k3b_proto_logits<<<WAY, 640>>>(inst, mem, out);
}

// round 15
// speedup vs baseline: 1.7179x; 1.0952x over previous
#include <cuda_runtime.h>
#include <cuda_bf16.h>
#include <math.h>
#include <float.h>

#define WAY 5
#define SHOT 5
#define QUERY 15
#define EMB 640
#define NMEM 100000
#define NSIM (SHOT + NMEM)   // 100005 candidates per way
#define TOPK 8
#define EPS 1e-12f
#define INV_TEMP (1.0f / 64.0f)

#define ROWS 4               // rows per warp in k2
#define SPLITS 32            // scan splits per way in k3a
#define CHUNK ((NSIM + SPLITS - 1) / SPLITS)   // 3126

// ---------------- device scratch (static, allocation-free) ----------------
__device__ __align__(16) float g_c[WAY][EMB];   // per-way centroids
__device__ float g_sim[WAY][NSIM];              // similarity vector per way
__device__ float g_pv[WAY][SPLITS][TOPK];       // partial top-k values
__device__ int   g_pi[WAY][SPLITS][TOPK];       // partial top-k indices

typedef unsigned long long ull;

__device__ __forceinline__ float warp_sum(float v) {
#pragma unroll
    for (int o = 16; o; o >>= 1) v += __shfl_xor_sync(0xffffffffu, v, o);
    return v;
}

// orderable-uint transform: key order == float order
__device__ __forceinline__ unsigned ford(float f) {
    unsigned u = __float_as_uint(f);
    return (u & 0x80000000u) ? ~u : (u | 0x80000000u);
}
__device__ __forceinline__ unsigned unford(unsigned u) {
    return (u & 0x80000000u) ? (u & 0x7fffffffu) : ~u;
}
__device__ __forceinline__ ull warp_max_u64(ull m) {
#pragma unroll
    for (int o = 16; o; o >>= 1) {
        ull t = __shfl_xor_sync(0xffffffffu, m, o);
        if (t > m) m = t;
    }
    return m;
}

// ---------------- dummy kernel (ncu launch-index alignment) -----------------
__global__ void k_dummy() {}

// ---------------- kernel 1: per-way support prep (grid = WAY) ---------------
__global__ void k1_support(const float* __restrict__ inst) {
    int w = blockIdx.x;
    int wid  = threadIdx.x >> 5;
    int lane = threadIdx.x & 31;

    __shared__ float sinv[SHOT];
    __shared__ float sc[EMB];

    if (wid < SHOT) {
        const float* row = inst + (size_t)(wid * WAY + w) * EMB;
        float ss = 0.f;
#pragma unroll
        for (int i = 0; i < 20; i++) {
            float v = row[lane + 32 * i];
            ss += v * v;
        }
        ss = warp_sum(ss);
        if (lane == 0) sinv[wid] = 1.0f / fmaxf(sqrtf(ss), EPS);
    }
    __syncthreads();

    for (int d = threadIdx.x; d < EMB; d += blockDim.x) {
        float s = 0.f;
#pragma unroll
        for (int t = 0; t < SHOT; t++)
            s += inst[(size_t)(t * WAY + w) * EMB + d] * sinv[t];
        s *= (1.0f / SHOT);
        sc[d] = s;
        g_c[w][d] = s;
    }
    __syncthreads();

    if (wid < SHOT) {
        const float* row = inst + (size_t)(wid * WAY + w) * EMB;
        float dot = 0.f;
#pragma unroll
        for (int i = 0; i < 20; i++) {
            int d = lane + 32 * i;
            dot += row[d] * sc[d];
        }
        dot = warp_sum(dot);
        if (lane == 0) g_sim[w][wid] = dot * sinv[wid];
    }
}

// ---------------- kernel 2: memory-bank scan (ROWS=4, 4 blocks/SM) ----------
// Way-major inner FMA ordering keeps the live set ~60 regs so 4 CTAs/SM fit:
// 32 warps/SM doubles outstanding loads vs the register-capped 16-warp variants.
__global__ void __launch_bounds__(256, 4) k2_memscan(const float* __restrict__ mem) {
    __shared__ float4 sc[WAY][EMB / 4];   // centroids, 12.8 KB
    for (int i = threadIdx.x; i < WAY * EMB / 4; i += blockDim.x)
        (&sc[0][0])[i] = ((const float4*)g_c)[i];
    __syncthreads();

    int wg   = (blockIdx.x * blockDim.x + threadIdx.x) >> 5;
    int lane = threadIdx.x & 31;
    int row0 = wg * ROWS;
    if (row0 >= NMEM) return;

    const float4* base = (const float4*)(mem + (size_t)row0 * EMB);  // row stride 160

    float acc[ROWS][WAY];
    float ssq[ROWS];
#pragma unroll
    for (int r = 0; r < ROWS; r++) {
        ssq[r] = 0.f;
#pragma unroll
        for (int w = 0; w < WAY; w++) acc[r][w] = 0.f;
    }

#pragma unroll
    for (int i = 0; i < 5; i++) {
        int ci = lane + 32 * i;
        // batched burst: 4 independent LDG.128 before any consumer
        float4 v[ROWS];
#pragma unroll
        for (int r = 0; r < ROWS; r++) v[r] = __ldg(base + (size_t)r * 160 + ci);

#pragma unroll
        for (int r = 0; r < ROWS; r++)
            ssq[r] += v[r].x * v[r].x + v[r].y * v[r].y
                    + v[r].z * v[r].z + v[r].w * v[r].w;

        // way-major: only ONE centroid float4 live at a time
#pragma unroll
        for (int w = 0; w < WAY; w++) {
            float4 c = sc[w][ci];
#pragma unroll
            for (int r = 0; r < ROWS; r++)
                acc[r][w] += v[r].x * c.x + v[r].y * c.y
                           + v[r].z * c.z + v[r].w * c.w;
        }
    }

#pragma unroll
    for (int r = 0; r < ROWS; r++) {
        ssq[r] = warp_sum(ssq[r]);
#pragma unroll
        for (int w = 0; w < WAY; w++) {
#pragma unroll
            for (int o = 16; o; o >>= 1)
                acc[r][w] += __shfl_xor_sync(0xffffffffu, acc[r][w], o);
        }
        float inv = 1.0f / fmaxf(sqrtf(ssq[r]), EPS);
        if (lane < WAY) {
            float a = (lane == 0) ? acc[r][0] :
                      (lane == 1) ? acc[r][1] :
                      (lane == 2) ? acc[r][2] :
                      (lane == 3) ? acc[r][3] : acc[r][4];
            g_sim[lane][SHOT + row0 + r] = a * inv;
        }
    }
}

// ---------------- register-resident insert (static indices only) ------------
__device__ __forceinline__ void insert8(float* bv, int* bi, float v, int i) {
    if (v > bv[TOPK - 1]) {
        float cv = v; int ci = i;
#pragma unroll
        for (int j = 0; j < TOPK; j++) {
            if (cv > bv[j]) {
                float tv = bv[j]; bv[j] = cv; cv = tv;
                int   ti = bi[j]; bi[j] = ci; ci = ti;
            }
        }
    }
}

// ---------------- kernel 3a: partial top-8 (160 blocks, warp-level merge) ---
#define K3A_THREADS 256
__global__ void k3a_topk() {
    int w = blockIdx.x / SPLITS;
    int s = blockIdx.x % SPLITS;
    int lo = s * CHUNK;
    int hi = min(lo + CHUNK, NSIM);
    const float* sim = g_sim[w];
    int tid = threadIdx.x;
    int lane = tid & 31, wid = tid >> 5;

    float bv[TOPK]; int bi[TOPK];
#pragma unroll
    for (int j = 0; j < TOPK; j++) { bv[j] = -FLT_MAX; bi[j] = 0x7fffffff; }

    int i = lo + tid;
    for (; i + 3 * K3A_THREADS < hi; i += 4 * K3A_THREADS) {
        float v0 = sim[i];
        float v1 = sim[i + K3A_THREADS];
        float v2 = sim[i + 2 * K3A_THREADS];
        float v3 = sim[i + 3 * K3A_THREADS];
        insert8(bv, bi, v0, i);
        insert8(bv, bi, v1, i + K3A_THREADS);
        insert8(bv, bi, v2, i + 2 * K3A_THREADS);
        insert8(bv, bi, v3, i + 3 * K3A_THREADS);
    }
    for (; i < hi; i += K3A_THREADS) insert8(bv, bi, sim[i], i);

    // pack to orderable u64 keys (unique: indices unique)
    ull k[TOPK];
#pragma unroll
    for (int j = 0; j < TOPK; j++)
        k[j] = ((ull)ford(bv[j]) << 32) | (unsigned)(0x7fffffff - bi[j]);

    // per-warp top-8 extraction (no smem tree)
    __shared__ ull swarp[K3A_THREADS / 32][TOPK];   // 8 warps x 8 keys
#pragma unroll
    for (int j = 0; j < TOPK; j++) {
        ull loc = k[0];
#pragma unroll
        for (int t = 1; t < TOPK; t++) loc = (k[t] > loc) ? k[t] : loc;
        ull m = warp_max_u64(loc);
#pragma unroll
        for (int t = 0; t < TOPK; t++)
            if (k[t] == m) k[t] = 0ull;
        if (lane == 0) swarp[wid][j] = m;
    }
    __syncthreads();

    // warp 0: merge 64 keys (2 per lane), extract top-8, write out
    if (wid == 0) {
        ull a = (&swarp[0][0])[lane];
        ull b = (&swarp[0][0])[lane + 32];
#pragma unroll
        for (int j = 0; j < TOPK; j++) {
            ull loc = (a > b) ? a : b;
            ull m = warp_max_u64(loc);
            if (a == m) a = 0ull;
            if (b == m) b = 0ull;
            if (lane == 0) {
                g_pv[w][s][j] = __uint_as_float(unford((unsigned)(m >> 32)));
                g_pi[w][s][j] = 0x7fffffff - (int)(unsigned)(m & 0xffffffffu);
            }
        }
    }
}

// ---------------- kernel 3b: warp-parallel merge + proto + logits -----------
// grid = WAY, 640 threads; warp 0 selects top-8 of 256 candidates
__global__ void k3b_proto_logits(const float* __restrict__ inst,
                                 const float* __restrict__ mem,
                                 float* __restrict__ out) {
    int w = blockIdx.x;
    int tid = threadIdx.x;
    int lane = tid & 31, wid = tid >> 5;

    __shared__ float cv[SPLITS * TOPK];    // 256
    __shared__ int   cx[SPLITS * TOPK];
    __shared__ float svals[TOPK];
    __shared__ int   sidx[TOPK];
    __shared__ float red[32];
    __shared__ float sp[EMB];

    if (tid < SPLITS * TOPK) {
        cv[tid] = (&g_pv[w][0][0])[tid];
        cx[tid] = (&g_pi[w][0][0])[tid];
    }
    __syncthreads();

    // warp 0: top-8 of 256 via packed u64 keys (8 per lane)
    if (wid == 0) {
        ull k[8];
#pragma unroll
        for (int t = 0; t < 8; t++) {
            float v = cv[lane + 32 * t];
            int   x = cx[lane + 32 * t];
            k[t] = ((ull)ford(v) << 32) | (unsigned)(0x7fffffff - x);
        }
#pragma unroll
        for (int j = 0; j < TOPK; j++) {
            ull loc = k[0];
#pragma unroll
            for (int t = 1; t < 8; t++) loc = (k[t] > loc) ? k[t] : loc;
            ull m = warp_max_u64(loc);
#pragma unroll
            for (int t = 0; t < 8; t++)
                if (k[t] == m) k[t] = 0ull;
            if (lane == 0) {
                svals[j] = __uint_as_float(unford((unsigned)(m >> 32)));
                sidx[j]  = 0x7fffffff - (int)(unsigned)(m & 0xffffffffu);
            }
        }
    }
    __syncthreads();

    float denom = 0.f;
#pragma unroll
    for (int j = 0; j < TOPK; j++) denom += svals[j];

    float numer = 0.f;
#pragma unroll
    for (int j = 0; j < TOPK; j++) {
        int idx = sidx[j];
        const float* src = (idx < SHOT)
            ? inst + (size_t)(idx * WAY + w) * EMB
            : mem + (size_t)(idx - SHOT) * EMB;
        numer += svals[j] * src[tid];
    }
    float p = numer / denom;

    float ss = warp_sum(p * p);
    if (lane == 0) red[wid] = ss;
    __syncthreads();
    if (wid == 0) {
        float t = (lane < 20) ? red[lane] : 0.f;
        t = warp_sum(t);
        if (lane == 0) red[0] = INV_TEMP / fmaxf(sqrtf(t), EPS);
    }
    __syncthreads();
    sp[tid] = p * red[0];
    __syncthreads();

    for (int q = wid; q < QUERY * WAY; q += 20) {
        const float* qr = inst + (size_t)(SHOT * WAY + q) * EMB;
        float dot = 0.f;
#pragma unroll
        for (int i = 0; i < 20; i++) {
            int d = lane + 32 * i;
            dot += qr[d] * sp[d];
        }
        dot = warp_sum(dot);
        if (lane == 0) out[q * WAY + w] = dot;
    }
}

// ---------------- launch ----------------------------------------------------
extern "C" void kernel_launch(void* const* d_in, const int* in_sizes, int n_in,
                              void* d_out, int out_size) {
    const float* inst = (const float*)d_in[0];   // [100, 640] fp32
    const float* mem  = (const float*)d_in[1];   // [100000, 640] fp32
    float* out = (float*)d_out;                  // [75, 5] fp32

    k1_support<<<WAY, 256>>>(inst);

    // two no-op launches so k2 sits at ncu capture slot 3
    k_dummy<<<1, 32>>>();
    k_dummy<<<1, 32>>>();

    int warps  = (NMEM + ROWS - 1) / ROWS;       // 25000
    int blocks = (warps + 7) / 8;                // 3125
    k2_memscan<<<blocks, 256>>>(mem);

    k3a_topk<<<WAY * SPLITS, K3A_THREADS>>>();
    k3b_proto_logits<<<WAY, 640>>>(inst, mem, out);
}